// round 12
// baseline (speedup 1.0000x reference)
#include <cuda_runtime.h>
#include <cuda_bf16.h>
#include <cuda_fp16.h>
#include <cuda_pipeline.h>
#include <mma.h>
#include <cstdint>

using namespace nvcuda;

#define NNODES 50000
#define MPAD   50048          // 391 * 128
#define EMAX   800000
#define DOUT   256
#define DIN    256

// ---------------------------------------------------------------------------
// Scratch (device globals)
// ---------------------------------------------------------------------------
__device__ __half g_h16[(size_t)MPAD * DOUT];    // x @ W in fp16 (gather source)
__device__ int   g_degi[NNODES];
__device__ int   g_off[NNODES];
__device__ int   g_cur[NNODES];
__device__ float g_dinv[NNODES];
__device__ int   g_csr[EMAX];
__device__ int   g_bsum[64];
__device__ __nv_bfloat16 g_a_hi[(size_t)MPAD * DIN];
__device__ __nv_bfloat16 g_a_lo[(size_t)MPAD * DIN];
__device__ __nv_bfloat16 g_wt_hi[DOUT * DIN];    // W^T [n][k], k contiguous
__device__ __nv_bfloat16 g_wt_lo[DOUT * DIN];

// ---------------------------------------------------------------------------
// Degree / CSR build
// ---------------------------------------------------------------------------
__global__ void k_zero(int n) {
    int i = blockIdx.x * blockDim.x + threadIdx.x;
    if (i < n) g_degi[i] = 0;
}
__global__ void k_count(const int* __restrict__ dst, int E) {
    int i = blockIdx.x * blockDim.x + threadIdx.x;
    if (i < E) atomicAdd(&g_degi[dst[i]], 1);
}

__global__ __launch_bounds__(1024) void k_scan1(int n) {
    __shared__ int wsum[32];
    int tid = threadIdx.x, lane = tid & 31, wid = tid >> 5;
    int i = blockIdx.x * 1024 + tid;
    int v = (i < n) ? g_degi[i] : 0;
    if (i < n) g_dinv[i] = rsqrtf((float)(v + 1));
    int sc = v;
    #pragma unroll
    for (int o = 1; o < 32; o <<= 1) {
        int t = __shfl_up_sync(0xffffffffu, sc, o);
        if (lane >= o) sc += t;
    }
    if (lane == 31) wsum[wid] = sc;
    __syncthreads();
    if (wid == 0) {
        int s = wsum[lane];
        #pragma unroll
        for (int o = 1; o < 32; o <<= 1) {
            int t = __shfl_up_sync(0xffffffffu, s, o);
            if (lane >= o) s += t;
        }
        wsum[lane] = s;
    }
    __syncthreads();
    int warpoff = (wid > 0) ? wsum[wid - 1] : 0;
    if (i < n) g_off[i] = warpoff + sc - v;
    if (tid == 0) g_bsum[blockIdx.x] = wsum[31];
}

__global__ void k_scan2(int nb) {
    __shared__ int w0tot;
    int t = threadIdx.x, lane = t & 31, wid = t >> 5;
    int v = (t < nb) ? g_bsum[t] : 0;
    int sc = v;
    #pragma unroll
    for (int o = 1; o < 32; o <<= 1) {
        int x = __shfl_up_sync(0xffffffffu, sc, o);
        if (lane >= o) sc += x;
    }
    if (wid == 0 && lane == 31) w0tot = sc;
    __syncthreads();
    int excl = sc - v + (wid ? w0tot : 0);
    if (t < nb) g_bsum[t] = excl;
}

__global__ __launch_bounds__(1024) void k_scan3(int n) {
    int i = blockIdx.x * 1024 + threadIdx.x;
    if (i >= n) return;
    int o = g_off[i] + g_bsum[blockIdx.x];
    g_off[i] = o;
    g_cur[i] = o;
}

__global__ void k_fill(const int* __restrict__ src,
                       const int* __restrict__ dst, int E) {
    int i = blockIdx.x * blockDim.x + threadIdx.x;
    if (i >= E) return;
    int d = dst[i];
    int pos = atomicAdd(&g_cur[d], 1);
    g_csr[pos] = src[i];
}

// ---------------------------------------------------------------------------
// Split prep (R8 versions)
// ---------------------------------------------------------------------------
__global__ void k_split(const float* __restrict__ x, int M) {
    int i = blockIdx.x * blockDim.x + threadIdx.x;   // uint4 index (8 bf16)
    int total = MPAD * DIN / 8;
    if (i >= total) return;
    int row = i >> 5;                                 // 32 uint4 per row
    float f[8];
    if (row < M) {
        const float4* p = (const float4*)(x + ((size_t)i << 3));
        float4 v0 = p[0], v1 = p[1];
        f[0] = v0.x; f[1] = v0.y; f[2] = v0.z; f[3] = v0.w;
        f[4] = v1.x; f[5] = v1.y; f[6] = v1.z; f[7] = v1.w;
    } else {
        #pragma unroll
        for (int j = 0; j < 8; j++) f[j] = 0.f;
    }
    uint32_t hi[4], lo[4];
    #pragma unroll
    for (int j = 0; j < 4; j++) {
        __nv_bfloat16 ha = __float2bfloat16_rn(f[j * 2]);
        __nv_bfloat16 hb = __float2bfloat16_rn(f[j * 2 + 1]);
        hi[j] = ((uint32_t)__bfloat16_as_ushort(hb) << 16) | __bfloat16_as_ushort(ha);
        __nv_bfloat16 la = __float2bfloat16_rn(f[j * 2] - __bfloat162float(ha));
        __nv_bfloat16 lb = __float2bfloat16_rn(f[j * 2 + 1] - __bfloat162float(hb));
        lo[j] = ((uint32_t)__bfloat16_as_ushort(lb) << 16) | __bfloat16_as_ushort(la);
    }
    ((uint4*)g_a_hi)[i] = make_uint4(hi[0], hi[1], hi[2], hi[3]);
    ((uint4*)g_a_lo)[i] = make_uint4(lo[0], lo[1], lo[2], lo[3]);
}

__global__ void k_wt(const float* __restrict__ W) {
    int i = blockIdx.x * blockDim.x + threadIdx.x;   // n*256 + k
    if (i >= DIN * DOUT) return;
    int n = i >> 8, k = i & 255;
    float w = W[k * DOUT + n];
    __nv_bfloat16 hi = __float2bfloat16_rn(w);
    g_wt_hi[i] = hi;
    g_wt_lo[i] = __float2bfloat16_rn(w - __bfloat162float(hi));
}

// ---------------------------------------------------------------------------
// WMMA GEMM (R8 mainloop, proven 82us) + fp16 epilogue via smem round-trip.
// ---------------------------------------------------------------------------
#define LDS 40
#define STAGE_ELEMS (128 * LDS)
#define STAGE_TOTAL (4 * STAGE_ELEMS)
#define SMEM_BYTES (2 * STAGE_TOTAL * 2)   // 81920 B; epilogue needs 65536 B

__global__ __launch_bounds__(256, 2) void k_gemm_wmma() {
    extern __shared__ __align__(16) __nv_bfloat16 smd[];

    const int tid = threadIdx.x;
    const int w = tid >> 5;
    const int warp_m = w & 3;
    const int warp_n = w >> 2;
    const int Rbase = blockIdx.x * 128;
    const int Nbase = blockIdx.y * 128;

    const int idx0 = tid * 2;
    const int r0 = idx0 >> 2, seg0 = idx0 & 3;
    const int r1 = (idx0 + 1) >> 2, seg1 = (idx0 + 1) & 3;

    auto prefetch = [&](int kc, int stage) {
        __nv_bfloat16* base = smd + stage * STAGE_TOTAL;
        __nv_bfloat16* dA_hi = base;
        __nv_bfloat16* dA_lo = base + STAGE_ELEMS;
        __nv_bfloat16* dB_hi = base + 2 * STAGE_ELEMS;
        __nv_bfloat16* dB_lo = base + 3 * STAGE_ELEMS;
        __pipeline_memcpy_async(dA_hi + r0 * LDS + seg0 * 8,
            (const uint4*)g_a_hi + (size_t)(Rbase + r0) * 32 + kc * 4 + seg0, 16);
        __pipeline_memcpy_async(dA_hi + r1 * LDS + seg1 * 8,
            (const uint4*)g_a_hi + (size_t)(Rbase + r1) * 32 + kc * 4 + seg1, 16);
        __pipeline_memcpy_async(dA_lo + r0 * LDS + seg0 * 8,
            (const uint4*)g_a_lo + (size_t)(Rbase + r0) * 32 + kc * 4 + seg0, 16);
        __pipeline_memcpy_async(dA_lo + r1 * LDS + seg1 * 8,
            (const uint4*)g_a_lo + (size_t)(Rbase + r1) * 32 + kc * 4 + seg1, 16);
        __pipeline_memcpy_async(dB_hi + r0 * LDS + seg0 * 8,
            (const uint4*)g_wt_hi + (size_t)(Nbase + r0) * 32 + kc * 4 + seg0, 16);
        __pipeline_memcpy_async(dB_hi + r1 * LDS + seg1 * 8,
            (const uint4*)g_wt_hi + (size_t)(Nbase + r1) * 32 + kc * 4 + seg1, 16);
        __pipeline_memcpy_async(dB_lo + r0 * LDS + seg0 * 8,
            (const uint4*)g_wt_lo + (size_t)(Nbase + r0) * 32 + kc * 4 + seg0, 16);
        __pipeline_memcpy_async(dB_lo + r1 * LDS + seg1 * 8,
            (const uint4*)g_wt_lo + (size_t)(Nbase + r1) * 32 + kc * 4 + seg1, 16);
        __pipeline_commit();
    };

    wmma::fragment<wmma::accumulator, 16, 16, 16, float> acc[2][4];
    #pragma unroll
    for (int mi = 0; mi < 2; mi++)
        #pragma unroll
        for (int ni = 0; ni < 4; ni++)
            wmma::fill_fragment(acc[mi][ni], 0.0f);

    prefetch(0, 0);

    for (int kc = 0; kc < 8; kc++) {
        if (kc < 7) prefetch(kc + 1, (kc + 1) & 1);
        __pipeline_wait_prior(kc < 7 ? 1 : 0);
        __syncthreads();

        __nv_bfloat16* base = smd + (kc & 1) * STAGE_TOTAL;
        __nv_bfloat16* sA_hi = base;
        __nv_bfloat16* sA_lo = base + STAGE_ELEMS;
        __nv_bfloat16* sB_hi = base + 2 * STAGE_ELEMS;
        __nv_bfloat16* sB_lo = base + 3 * STAGE_ELEMS;

        #pragma unroll
        for (int kk = 0; kk < 32; kk += 16) {
            wmma::fragment<wmma::matrix_a, 16, 16, 16, __nv_bfloat16, wmma::row_major> ah[2], al[2];
            #pragma unroll
            for (int mi = 0; mi < 2; mi++) {
                wmma::load_matrix_sync(ah[mi], sA_hi + (warp_m * 32 + mi * 16) * LDS + kk, LDS);
                wmma::load_matrix_sync(al[mi], sA_lo + (warp_m * 32 + mi * 16) * LDS + kk, LDS);
            }
            wmma::fragment<wmma::matrix_b, 16, 16, 16, __nv_bfloat16, wmma::col_major> bf[4];
            #pragma unroll
            for (int ni = 0; ni < 4; ni++)
                wmma::load_matrix_sync(bf[ni], sB_hi + (warp_n * 64 + ni * 16) * LDS + kk, LDS);
            #pragma unroll
            for (int mi = 0; mi < 2; mi++)
                #pragma unroll
                for (int ni = 0; ni < 4; ni++) {
                    wmma::mma_sync(acc[mi][ni], ah[mi], bf[ni], acc[mi][ni]);
                    wmma::mma_sync(acc[mi][ni], al[mi], bf[ni], acc[mi][ni]);
                }
            #pragma unroll
            for (int ni = 0; ni < 4; ni++)
                wmma::load_matrix_sync(bf[ni], sB_lo + (warp_n * 64 + ni * 16) * LDS + kk, LDS);
            #pragma unroll
            for (int mi = 0; mi < 2; mi++)
                #pragma unroll
                for (int ni = 0; ni < 4; ni++)
                    wmma::mma_sync(acc[mi][ni], ah[mi], bf[ni], acc[mi][ni]);
        }
        __syncthreads();
    }

    // ---- fp16 epilogue: frags -> smem fp32 tile [128][128] -> g_h16 ----
    float* sOut = (float*)smd;          // 65536 B <= 81920 B
    #pragma unroll
    for (int mi = 0; mi < 2; mi++)
        #pragma unroll
        for (int ni = 0; ni < 4; ni++)
            wmma::store_matrix_sync(
                sOut + (warp_m * 32 + mi * 16) * 128 + warp_n * 64 + ni * 16,
                acc[mi][ni], 128, wmma::mem_row_major);
    __syncthreads();

    // 2048 uint4 chunks (row, 8 halves); 8 per thread
    #pragma unroll
    for (int j = 0; j < 8; j++) {
        int c = tid * 8 + j;
        int row = c >> 4;              // 16 chunks per row
        int u = c & 15;
        const float* src = sOut + row * 128 + u * 8;
        __half2 h[4];
        #pragma unroll
        for (int q = 0; q < 4; q++)
            h[q] = __floats2half2_rn(src[q * 2], src[q * 2 + 1]);
        *(uint4*)(g_h16 + (size_t)(Rbase + row) * DOUT + Nbase + u * 8) =
            *(const uint4*)h;
    }
}

// ---------------------------------------------------------------------------
// Node kernel: one warp per node, fp16 gather (1 uint4 = 8 halves per lane
// per row), fp32 accumulate, fused bias+BN+ReLU.
// ---------------------------------------------------------------------------
__device__ __forceinline__ void fma8h(uint4 v, float s, float* acc) {
    const __half2* h = (const __half2*)&v;
    #pragma unroll
    for (int q = 0; q < 4; q++) {
        float2 f = __half22float2(h[q]);
        acc[2 * q]     = fmaf(f.x, s, acc[2 * q]);
        acc[2 * q + 1] = fmaf(f.y, s, acc[2 * q + 1]);
    }
}

__global__ __launch_bounds__(256) void k_node(float* __restrict__ out,
                                              const float* __restrict__ b,
                                              const float* __restrict__ gamma,
                                              const float* __restrict__ beta,
                                              const float* __restrict__ mean,
                                              const float* __restrict__ var,
                                              int n) {
    int warp = (blockIdx.x * blockDim.x + threadIdx.x) >> 5;
    int lane = threadIdx.x & 31;
    if (warp >= n) return;

    int node = warp;
    int start = g_off[node];
    int end   = start + g_degi[node];

    float acc[8] = {0.f, 0.f, 0.f, 0.f, 0.f, 0.f, 0.f, 0.f};

    int e = start;
    for (; e + 3 < end; e += 4) {
        int s0 = g_csr[e + 0], s1 = g_csr[e + 1];
        int s2 = g_csr[e + 2], s3 = g_csr[e + 3];
        float w0 = g_dinv[s0], w1 = g_dinv[s1];
        float w2 = g_dinv[s2], w3 = g_dinv[s3];
        uint4 a = __ldg((const uint4*)(g_h16 + (size_t)s0 * DOUT) + lane);
        uint4 c = __ldg((const uint4*)(g_h16 + (size_t)s1 * DOUT) + lane);
        uint4 d = __ldg((const uint4*)(g_h16 + (size_t)s2 * DOUT) + lane);
        uint4 f = __ldg((const uint4*)(g_h16 + (size_t)s3 * DOUT) + lane);
        fma8h(a, w0, acc);
        fma8h(c, w1, acc);
        fma8h(d, w2, acc);
        fma8h(f, w3, acc);
    }
    for (; e < end; e++) {
        int s0 = g_csr[e];
        float w0 = g_dinv[s0];
        uint4 a = __ldg((const uint4*)(g_h16 + (size_t)s0 * DOUT) + lane);
        fma8h(a, w0, acc);
    }

    float di = g_dinv[node];
    {
        uint4 a = __ldg((const uint4*)(g_h16 + (size_t)node * DOUT) + lane);
        fma8h(a, di, acc);
    }
    #pragma unroll
    for (int k = 0; k < 8; k++) acc[k] *= di;

    // bias + BN + ReLU; lane covers channels [8*lane, 8*lane+8)
    #pragma unroll
    for (int half = 0; half < 2; half++) {
        int c4 = lane * 2 + half;
        float4 bv = ((const float4*)b)[c4];
        float4 gv = ((const float4*)gamma)[c4];
        float4 tv = ((const float4*)beta)[c4];
        float4 mv = ((const float4*)mean)[c4];
        float4 vv = ((const float4*)var)[c4];
        const float* a = acc + half * 4;
        float4 r;
        float sx = gv.x * rsqrtf(vv.x + 1e-5f);
        float sy = gv.y * rsqrtf(vv.y + 1e-5f);
        float sz = gv.z * rsqrtf(vv.z + 1e-5f);
        float sw = gv.w * rsqrtf(vv.w + 1e-5f);
        r.x = fmaxf(fmaf(a[0] + bv.x - mv.x, sx, tv.x), 0.f);
        r.y = fmaxf(fmaf(a[1] + bv.y - mv.y, sy, tv.y), 0.f);
        r.z = fmaxf(fmaf(a[2] + bv.z - mv.z, sz, tv.z), 0.f);
        r.w = fmaxf(fmaf(a[3] + bv.w - mv.w, sw, tv.w), 0.f);
        ((float4*)(out + (size_t)node * DOUT))[c4] = r;
    }
}

// ---------------------------------------------------------------------------
// Two-stream DAG:
//   main:  wt -> split -> gemm --------------------------+-> node
//   s2:    zero -> count -> scan1/2/3 -> fill -----------+
// gemm stays 4th <<<>>> for the ncu profile slot.
// ---------------------------------------------------------------------------
extern "C" void kernel_launch(void* const* d_in, const int* in_sizes, int n_in,
                              void* d_out, int out_size) {
    const float* x      = (const float*)d_in[0];
    const int*   ei     = (const int*)d_in[1];   // int32 (jax x64 disabled)
    const float* W      = (const float*)d_in[2];
    const float* b      = (const float*)d_in[3];
    const float* gamma  = (const float*)d_in[4];
    const float* beta   = (const float*)d_in[5];
    const float* rmean  = (const float*)d_in[6];
    const float* rvar   = (const float*)d_in[7];
    float* out = (float*)d_out;

    int N = in_sizes[0] / DIN;     // 50000
    int E = in_sizes[1] / 2;       // 800000
    const int* src = ei;
    const int* dst = ei + E;
    int nb = (N + 1023) / 1024;

    static cudaStream_t s2;
    static cudaEvent_t ev_fork, ev_join;
    static bool init_done = false;
    if (!init_done) {
        cudaFuncSetAttribute(k_gemm_wmma,
                             cudaFuncAttributeMaxDynamicSharedMemorySize,
                             SMEM_BYTES);
        cudaStreamCreateWithFlags(&s2, cudaStreamNonBlocking);
        cudaEventCreateWithFlags(&ev_fork, cudaEventDisableTiming);
        cudaEventCreateWithFlags(&ev_join, cudaEventDisableTiming);
        init_done = true;
    }

    // fork
    cudaEventRecord(ev_fork, 0);
    cudaStreamWaitEvent(s2, ev_fork, 0);

    k_wt<<<(DIN * DOUT + 255) / 256, 256>>>(W);                    // launch 1
    int splitn = MPAD * DIN / 8;
    k_split<<<(splitn + 255) / 256, 256>>>(x, N);                  // launch 2
    k_zero<<<(N + 255) / 256, 256, 0, s2>>>(N);                    // launch 3

    dim3 ggrid(MPAD / 128, DOUT / 128);
    k_gemm_wmma<<<ggrid, 256, SMEM_BYTES>>>();                     // launch 4

    k_count<<<(E + 255) / 256, 256, 0, s2>>>(dst, E);
    k_scan1<<<nb, 1024, 0, s2>>>(N);
    k_scan2<<<1, 64, 0, s2>>>(nb);
    k_scan3<<<nb, 1024, 0, s2>>>(N);
    k_fill<<<(E + 255) / 256, 256, 0, s2>>>(src, dst, E);

    // join
    cudaEventRecord(ev_join, s2);
    cudaStreamWaitEvent(0, ev_join, 0);

    long long nthreads = (long long)N * 32;
    k_node<<<(int)((nthreads + 255) / 256), 256>>>(out, b, gamma, beta,
                                                   rmean, rvar, N);
}

// round 13
// speedup vs baseline: 1.1137x; 1.1137x over previous
#include <cuda_runtime.h>
#include <cuda_bf16.h>
#include <cuda_fp16.h>
#include <cuda_pipeline.h>
#include <mma.h>
#include <cstdint>

using namespace nvcuda;

#define NNODES 50000
#define MPAD   50048          // 391 * 128
#define EMAX   800000
#define DOUT   256
#define DIN    256

// ---------------------------------------------------------------------------
// Scratch (device globals)
// ---------------------------------------------------------------------------
__device__ __half g_h16[(size_t)MPAD * DOUT];    // x @ W in fp16 (gather source)
__device__ int   g_degi[NNODES];
__device__ int   g_off[NNODES];
__device__ int   g_cur[NNODES];
__device__ float g_dinv[NNODES];
__device__ int   g_csr[EMAX];
__device__ int   g_bsum[64];
__device__ __nv_bfloat16 g_a_hi[(size_t)MPAD * DIN];
__device__ __nv_bfloat16 g_a_lo[(size_t)MPAD * DIN];
__device__ __nv_bfloat16 g_wt_hi[DOUT * DIN];    // W^T [n][k], k contiguous
__device__ __nv_bfloat16 g_wt_lo[DOUT * DIN];

// ---------------------------------------------------------------------------
// Degree / CSR build
// ---------------------------------------------------------------------------
__global__ void k_zero(int n) {
    int i = blockIdx.x * blockDim.x + threadIdx.x;
    if (i < n) g_degi[i] = 0;
}
__global__ void k_count(const int* __restrict__ dst, int E) {
    int i = blockIdx.x * blockDim.x + threadIdx.x;
    if (i < E) atomicAdd(&g_degi[dst[i]], 1);
}

__global__ __launch_bounds__(1024) void k_scan1(int n) {
    __shared__ int wsum[32];
    int tid = threadIdx.x, lane = tid & 31, wid = tid >> 5;
    int i = blockIdx.x * 1024 + tid;
    int v = (i < n) ? g_degi[i] : 0;
    if (i < n) g_dinv[i] = rsqrtf((float)(v + 1));
    int sc = v;
    #pragma unroll
    for (int o = 1; o < 32; o <<= 1) {
        int t = __shfl_up_sync(0xffffffffu, sc, o);
        if (lane >= o) sc += t;
    }
    if (lane == 31) wsum[wid] = sc;
    __syncthreads();
    if (wid == 0) {
        int s = wsum[lane];
        #pragma unroll
        for (int o = 1; o < 32; o <<= 1) {
            int t = __shfl_up_sync(0xffffffffu, s, o);
            if (lane >= o) s += t;
        }
        wsum[lane] = s;
    }
    __syncthreads();
    int warpoff = (wid > 0) ? wsum[wid - 1] : 0;
    if (i < n) g_off[i] = warpoff + sc - v;
    if (tid == 0) g_bsum[blockIdx.x] = wsum[31];
}

__global__ void k_scan2(int nb) {
    __shared__ int w0tot;
    int t = threadIdx.x, lane = t & 31, wid = t >> 5;
    int v = (t < nb) ? g_bsum[t] : 0;
    int sc = v;
    #pragma unroll
    for (int o = 1; o < 32; o <<= 1) {
        int x = __shfl_up_sync(0xffffffffu, sc, o);
        if (lane >= o) sc += x;
    }
    if (wid == 0 && lane == 31) w0tot = sc;
    __syncthreads();
    int excl = sc - v + (wid ? w0tot : 0);
    if (t < nb) g_bsum[t] = excl;
}

__global__ __launch_bounds__(1024) void k_scan3(int n) {
    int i = blockIdx.x * 1024 + threadIdx.x;
    if (i >= n) return;
    int o = g_off[i] + g_bsum[blockIdx.x];
    g_off[i] = o;
    g_cur[i] = o;
}

__global__ void k_fill(const int* __restrict__ src,
                       const int* __restrict__ dst, int E) {
    int i = blockIdx.x * blockDim.x + threadIdx.x;
    if (i >= E) return;
    int d = dst[i];
    int pos = atomicAdd(&g_cur[d], 1);
    g_csr[pos] = src[i];
}

// ---------------------------------------------------------------------------
// Split prep
// ---------------------------------------------------------------------------
__global__ void k_split(const float* __restrict__ x, int M) {
    int i = blockIdx.x * blockDim.x + threadIdx.x;   // uint4 index (8 bf16)
    int total = MPAD * DIN / 8;
    if (i >= total) return;
    int row = i >> 5;                                 // 32 uint4 per row
    float f[8];
    if (row < M) {
        const float4* p = (const float4*)(x + ((size_t)i << 3));
        float4 v0 = p[0], v1 = p[1];
        f[0] = v0.x; f[1] = v0.y; f[2] = v0.z; f[3] = v0.w;
        f[4] = v1.x; f[5] = v1.y; f[6] = v1.z; f[7] = v1.w;
    } else {
        #pragma unroll
        for (int j = 0; j < 8; j++) f[j] = 0.f;
    }
    uint32_t hi[4], lo[4];
    #pragma unroll
    for (int j = 0; j < 4; j++) {
        __nv_bfloat16 ha = __float2bfloat16_rn(f[j * 2]);
        __nv_bfloat16 hb = __float2bfloat16_rn(f[j * 2 + 1]);
        hi[j] = ((uint32_t)__bfloat16_as_ushort(hb) << 16) | __bfloat16_as_ushort(ha);
        __nv_bfloat16 la = __float2bfloat16_rn(f[j * 2] - __bfloat162float(ha));
        __nv_bfloat16 lb = __float2bfloat16_rn(f[j * 2 + 1] - __bfloat162float(hb));
        lo[j] = ((uint32_t)__bfloat16_as_ushort(lb) << 16) | __bfloat16_as_ushort(la);
    }
    ((uint4*)g_a_hi)[i] = make_uint4(hi[0], hi[1], hi[2], hi[3]);
    ((uint4*)g_a_lo)[i] = make_uint4(lo[0], lo[1], lo[2], lo[3]);
}

__global__ void k_wt(const float* __restrict__ W) {
    int i = blockIdx.x * blockDim.x + threadIdx.x;   // n*256 + k
    if (i >= DIN * DOUT) return;
    int n = i >> 8, k = i & 255;
    float w = W[k * DOUT + n];
    __nv_bfloat16 hi = __float2bfloat16_rn(w);
    g_wt_hi[i] = hi;
    g_wt_lo[i] = __float2bfloat16_rn(w - __bfloat162float(hi));
}

// ---------------------------------------------------------------------------
// WMMA GEMM half: computes 128 output columns starting at nbase.
// Mainloop = R8 proven form. Epilogue: padded smem (stride 132, no bank
// conflicts) + lane-contiguous fp16 global writes.
// ---------------------------------------------------------------------------
#define LDS 40
#define STAGE_ELEMS (128 * LDS)
#define STAGE_TOTAL (4 * STAGE_ELEMS)
#define SOUT_LD 132
#define SMEM_BYTES (2 * STAGE_TOTAL * 2)   // 81920 B; epilogue needs 128*132*4=67584

__global__ __launch_bounds__(256, 2) void k_gemm_wmma(int nbase) {
    extern __shared__ __align__(16) __nv_bfloat16 smd[];

    const int tid = threadIdx.x;
    const int w = tid >> 5;
    const int warp_m = w & 3;
    const int warp_n = w >> 2;
    const int Rbase = blockIdx.x * 128;
    const int Nbase = nbase;

    const int idx0 = tid * 2;
    const int r0 = idx0 >> 2, seg0 = idx0 & 3;
    const int r1 = (idx0 + 1) >> 2, seg1 = (idx0 + 1) & 3;

    auto prefetch = [&](int kc, int stage) {
        __nv_bfloat16* base = smd + stage * STAGE_TOTAL;
        __nv_bfloat16* dA_hi = base;
        __nv_bfloat16* dA_lo = base + STAGE_ELEMS;
        __nv_bfloat16* dB_hi = base + 2 * STAGE_ELEMS;
        __nv_bfloat16* dB_lo = base + 3 * STAGE_ELEMS;
        __pipeline_memcpy_async(dA_hi + r0 * LDS + seg0 * 8,
            (const uint4*)g_a_hi + (size_t)(Rbase + r0) * 32 + kc * 4 + seg0, 16);
        __pipeline_memcpy_async(dA_hi + r1 * LDS + seg1 * 8,
            (const uint4*)g_a_hi + (size_t)(Rbase + r1) * 32 + kc * 4 + seg1, 16);
        __pipeline_memcpy_async(dA_lo + r0 * LDS + seg0 * 8,
            (const uint4*)g_a_lo + (size_t)(Rbase + r0) * 32 + kc * 4 + seg0, 16);
        __pipeline_memcpy_async(dA_lo + r1 * LDS + seg1 * 8,
            (const uint4*)g_a_lo + (size_t)(Rbase + r1) * 32 + kc * 4 + seg1, 16);
        __pipeline_memcpy_async(dB_hi + r0 * LDS + seg0 * 8,
            (const uint4*)g_wt_hi + (size_t)(Nbase + r0) * 32 + kc * 4 + seg0, 16);
        __pipeline_memcpy_async(dB_hi + r1 * LDS + seg1 * 8,
            (const uint4*)g_wt_hi + (size_t)(Nbase + r1) * 32 + kc * 4 + seg1, 16);
        __pipeline_memcpy_async(dB_lo + r0 * LDS + seg0 * 8,
            (const uint4*)g_wt_lo + (size_t)(Nbase + r0) * 32 + kc * 4 + seg0, 16);
        __pipeline_memcpy_async(dB_lo + r1 * LDS + seg1 * 8,
            (const uint4*)g_wt_lo + (size_t)(Nbase + r1) * 32 + kc * 4 + seg1, 16);
        __pipeline_commit();
    };

    wmma::fragment<wmma::accumulator, 16, 16, 16, float> acc[2][4];
    #pragma unroll
    for (int mi = 0; mi < 2; mi++)
        #pragma unroll
        for (int ni = 0; ni < 4; ni++)
            wmma::fill_fragment(acc[mi][ni], 0.0f);

    prefetch(0, 0);

    for (int kc = 0; kc < 8; kc++) {
        if (kc < 7) prefetch(kc + 1, (kc + 1) & 1);
        __pipeline_wait_prior(kc < 7 ? 1 : 0);
        __syncthreads();

        __nv_bfloat16* base = smd + (kc & 1) * STAGE_TOTAL;
        __nv_bfloat16* sA_hi = base;
        __nv_bfloat16* sA_lo = base + STAGE_ELEMS;
        __nv_bfloat16* sB_hi = base + 2 * STAGE_ELEMS;
        __nv_bfloat16* sB_lo = base + 3 * STAGE_ELEMS;

        #pragma unroll
        for (int kk = 0; kk < 32; kk += 16) {
            wmma::fragment<wmma::matrix_a, 16, 16, 16, __nv_bfloat16, wmma::row_major> ah[2], al[2];
            #pragma unroll
            for (int mi = 0; mi < 2; mi++) {
                wmma::load_matrix_sync(ah[mi], sA_hi + (warp_m * 32 + mi * 16) * LDS + kk, LDS);
                wmma::load_matrix_sync(al[mi], sA_lo + (warp_m * 32 + mi * 16) * LDS + kk, LDS);
            }
            wmma::fragment<wmma::matrix_b, 16, 16, 16, __nv_bfloat16, wmma::col_major> bf[4];
            #pragma unroll
            for (int ni = 0; ni < 4; ni++)
                wmma::load_matrix_sync(bf[ni], sB_hi + (warp_n * 64 + ni * 16) * LDS + kk, LDS);
            #pragma unroll
            for (int mi = 0; mi < 2; mi++)
                #pragma unroll
                for (int ni = 0; ni < 4; ni++) {
                    wmma::mma_sync(acc[mi][ni], ah[mi], bf[ni], acc[mi][ni]);
                    wmma::mma_sync(acc[mi][ni], al[mi], bf[ni], acc[mi][ni]);
                }
            #pragma unroll
            for (int ni = 0; ni < 4; ni++)
                wmma::load_matrix_sync(bf[ni], sB_lo + (warp_n * 64 + ni * 16) * LDS + kk, LDS);
            #pragma unroll
            for (int mi = 0; mi < 2; mi++)
                #pragma unroll
                for (int ni = 0; ni < 4; ni++)
                    wmma::mma_sync(acc[mi][ni], ah[mi], bf[ni], acc[mi][ni]);
        }
        __syncthreads();
    }

    // ---- fp16 epilogue: frags -> padded smem tile -> coalesced writes ----
    float* sOut = (float*)smd;          // 128 x SOUT_LD floats = 67584 B
    #pragma unroll
    for (int mi = 0; mi < 2; mi++)
        #pragma unroll
        for (int ni = 0; ni < 4; ni++)
            wmma::store_matrix_sync(
                sOut + (warp_m * 32 + mi * 16) * SOUT_LD + warp_n * 64 + ni * 16,
                acc[mi][ni], SOUT_LD, wmma::mem_row_major);
    __syncthreads();

    // 2048 uint4 chunks; lane-contiguous: c = j*256 + tid
    #pragma unroll
    for (int j = 0; j < 8; j++) {
        int c = j * 256 + tid;
        int row = c >> 4;              // 16 chunks (of 8 halves) per 128-col row
        int u = c & 15;
        const float* src = sOut + row * SOUT_LD + u * 8;
        __half2 h[4];
        #pragma unroll
        for (int q = 0; q < 4; q++)
            h[q] = __floats2half2_rn(src[q * 2], src[q * 2 + 1]);
        *(uint4*)(g_h16 + (size_t)(Rbase + row) * DOUT + Nbase + u * 8) =
            *(const uint4*)h;
    }
}

// ---------------------------------------------------------------------------
// Node kernel half: one warp per node, 128 columns starting at col_base.
// Lane reads uint2 (4 halves) per row; 8-edge unroll (8 outstanding loads).
// ---------------------------------------------------------------------------
__device__ __forceinline__ void fma4h(uint2 v, float s, float* acc) {
    const __half2* h = (const __half2*)&v;
    float2 f0 = __half22float2(h[0]);
    float2 f1 = __half22float2(h[1]);
    acc[0] = fmaf(f0.x, s, acc[0]);
    acc[1] = fmaf(f0.y, s, acc[1]);
    acc[2] = fmaf(f1.x, s, acc[2]);
    acc[3] = fmaf(f1.y, s, acc[3]);
}

__global__ __launch_bounds__(256) void k_node(float* __restrict__ out,
                                              const float* __restrict__ b,
                                              const float* __restrict__ gamma,
                                              const float* __restrict__ beta,
                                              const float* __restrict__ mean,
                                              const float* __restrict__ var,
                                              int n, int col_base) {
    int warp = (blockIdx.x * blockDim.x + threadIdx.x) >> 5;
    int lane = threadIdx.x & 31;
    if (warp >= n) return;

    int node = warp;
    int start = g_off[node];
    int end   = start + g_degi[node];
    const size_t lane_off = col_base / 4 + lane;   // uint2 index within row

    float acc[4] = {0.f, 0.f, 0.f, 0.f};

    int e = start;
    for (; e + 7 < end; e += 8) {
        int   s[8];
        float wgt[8];
        uint2 v[8];
        #pragma unroll
        for (int q = 0; q < 8; q++) s[q] = g_csr[e + q];
        #pragma unroll
        for (int q = 0; q < 8; q++) wgt[q] = g_dinv[s[q]];
        #pragma unroll
        for (int q = 0; q < 8; q++)
            v[q] = __ldg((const uint2*)(g_h16 + (size_t)s[q] * DOUT) + lane_off);
        #pragma unroll
        for (int q = 0; q < 8; q++) fma4h(v[q], wgt[q], acc);
    }
    for (; e < end; e++) {
        int s0 = g_csr[e];
        float w0 = g_dinv[s0];
        uint2 a = __ldg((const uint2*)(g_h16 + (size_t)s0 * DOUT) + lane_off);
        fma4h(a, w0, acc);
    }

    float di = g_dinv[node];
    {
        uint2 a = __ldg((const uint2*)(g_h16 + (size_t)node * DOUT) + lane_off);
        fma4h(a, di, acc);
    }
    #pragma unroll
    for (int k = 0; k < 4; k++) acc[k] *= di;

    // bias + BN + ReLU; lane covers channels [col_base + 4*lane, +4)
    int c4 = (col_base >> 2) + lane;
    float4 bv = ((const float4*)b)[c4];
    float4 gv = ((const float4*)gamma)[c4];
    float4 tv = ((const float4*)beta)[c4];
    float4 mv = ((const float4*)mean)[c4];
    float4 vv = ((const float4*)var)[c4];
    float4 r;
    float sx = gv.x * rsqrtf(vv.x + 1e-5f);
    float sy = gv.y * rsqrtf(vv.y + 1e-5f);
    float sz = gv.z * rsqrtf(vv.z + 1e-5f);
    float sw = gv.w * rsqrtf(vv.w + 1e-5f);
    r.x = fmaxf(fmaf(acc[0] + bv.x - mv.x, sx, tv.x), 0.f);
    r.y = fmaxf(fmaf(acc[1] + bv.y - mv.y, sy, tv.y), 0.f);
    r.z = fmaxf(fmaf(acc[2] + bv.z - mv.z, sz, tv.z), 0.f);
    r.w = fmaxf(fmaf(acc[3] + bv.w - mv.w, sw, tv.w), 0.f);
    ((float4*)(out + (size_t)node * DOUT))[c4] = r;
}

// ---------------------------------------------------------------------------
// Column-split pipeline:
//   main: wt -> split -> gemm0 -> gemm1 -> (wait csr) node1 -> (wait n0)
//   s2:   zero -> count -> scan1/2/3 -> fill            [ev_csr]
//   s3:   (wait ev_g0, ev_csr) node0   -- runs concurrent with gemm1
// ---------------------------------------------------------------------------
extern "C" void kernel_launch(void* const* d_in, const int* in_sizes, int n_in,
                              void* d_out, int out_size) {
    const float* x      = (const float*)d_in[0];
    const int*   ei     = (const int*)d_in[1];   // int32 (jax x64 disabled)
    const float* W      = (const float*)d_in[2];
    const float* b      = (const float*)d_in[3];
    const float* gamma  = (const float*)d_in[4];
    const float* beta   = (const float*)d_in[5];
    const float* rmean  = (const float*)d_in[6];
    const float* rvar   = (const float*)d_in[7];
    float* out = (float*)d_out;

    int N = in_sizes[0] / DIN;     // 50000
    int E = in_sizes[1] / 2;       // 800000
    const int* src = ei;
    const int* dst = ei + E;
    int nb = (N + 1023) / 1024;

    static cudaStream_t s2, s3;
    static cudaEvent_t ev_fork, ev_csr, ev_g0, ev_n0;
    static bool init_done = false;
    if (!init_done) {
        cudaFuncSetAttribute(k_gemm_wmma,
                             cudaFuncAttributeMaxDynamicSharedMemorySize,
                             SMEM_BYTES);
        cudaStreamCreateWithFlags(&s2, cudaStreamNonBlocking);
        cudaStreamCreateWithFlags(&s3, cudaStreamNonBlocking);
        cudaEventCreateWithFlags(&ev_fork, cudaEventDisableTiming);
        cudaEventCreateWithFlags(&ev_csr, cudaEventDisableTiming);
        cudaEventCreateWithFlags(&ev_g0, cudaEventDisableTiming);
        cudaEventCreateWithFlags(&ev_n0, cudaEventDisableTiming);
        init_done = true;
    }

    long long nthreads = (long long)N * 32;
    int node_blocks = (int)((nthreads + 255) / 256);
    dim3 ggrid(MPAD / 128, 1);

    // fork
    cudaEventRecord(ev_fork, 0);
    cudaStreamWaitEvent(s2, ev_fork, 0);
    cudaStreamWaitEvent(s3, ev_fork, 0);

    k_wt<<<(DIN * DOUT + 255) / 256, 256>>>(W);                    // launch 1
    int splitn = MPAD * DIN / 8;
    k_split<<<(splitn + 255) / 256, 256>>>(x, N);                  // launch 2
    k_zero<<<(N + 255) / 256, 256, 0, s2>>>(N);                    // launch 3

    k_gemm_wmma<<<ggrid, 256, SMEM_BYTES>>>(0);                    // launch 4 (profile)
    cudaEventRecord(ev_g0, 0);

    // CSR chain on s2
    k_count<<<(E + 255) / 256, 256, 0, s2>>>(dst, E);
    k_scan1<<<nb, 1024, 0, s2>>>(N);
    k_scan2<<<1, 64, 0, s2>>>(nb);
    k_scan3<<<nb, 1024, 0, s2>>>(N);
    k_fill<<<(E + 255) / 256, 256, 0, s2>>>(src, dst, E);
    cudaEventRecord(ev_csr, s2);

    // gemm1 on main, node0 on s3 (concurrent)
    k_gemm_wmma<<<ggrid, 256, SMEM_BYTES>>>(128);
    cudaStreamWaitEvent(s3, ev_g0, 0);
    cudaStreamWaitEvent(s3, ev_csr, 0);
    k_node<<<node_blocks, 256, 0, s3>>>(out, b, gamma, beta, rmean, rvar, N, 0);
    cudaEventRecord(ev_n0, s3);

    // node1 on main after gemm1 + csr
    cudaStreamWaitEvent(0, ev_csr, 0);
    k_node<<<node_blocks, 256, 0, 0>>>(out, b, gamma, beta, rmean, rvar, N, 128);

    // join node0 back into origin stream
    cudaStreamWaitEvent(0, ev_n0, 0);
}

// round 14
// speedup vs baseline: 1.3338x; 1.1977x over previous
#include <cuda_runtime.h>
#include <cuda_fp16.h>
#include <cuda_pipeline.h>
#include <mma.h>
#include <cstdint>

using namespace nvcuda;

#define NNODES 50000
#define MPAD   50048          // 391 * 128
#define EMAX   800000
#define DOUT   256
#define DIN    256

// ---------------------------------------------------------------------------
// Scratch (device globals)
// ---------------------------------------------------------------------------
__device__ __half g_h16[(size_t)MPAD * DOUT];    // x @ W in fp16 (gather source)
__device__ int   g_degi[NNODES];
__device__ int   g_off[NNODES];
__device__ int   g_cur[NNODES];
__device__ float g_dinv[NNODES];
__device__ int   g_csr[EMAX];
__device__ int   g_bsum[64];
__device__ __half g_a_hi[(size_t)MPAD * DIN];    // x hi (fp16)
__device__ __half g_a_lo[(size_t)MPAD * DIN];    // x residual (fp16)
__device__ __half g_wt16[DOUT * DIN];            // W^T fp16 [n][k]

// ---------------------------------------------------------------------------
// Degree / CSR build
// ---------------------------------------------------------------------------
__global__ void k_zero(int n) {
    int i = blockIdx.x * blockDim.x + threadIdx.x;
    if (i < n) g_degi[i] = 0;
}
__global__ void k_count(const int* __restrict__ dst, int E) {
    int i = blockIdx.x * blockDim.x + threadIdx.x;
    if (i < E) atomicAdd(&g_degi[dst[i]], 1);
}

__global__ __launch_bounds__(1024) void k_scan1(int n) {
    __shared__ int wsum[32];
    int tid = threadIdx.x, lane = tid & 31, wid = tid >> 5;
    int i = blockIdx.x * 1024 + tid;
    int v = (i < n) ? g_degi[i] : 0;
    if (i < n) g_dinv[i] = rsqrtf((float)(v + 1));
    int sc = v;
    #pragma unroll
    for (int o = 1; o < 32; o <<= 1) {
        int t = __shfl_up_sync(0xffffffffu, sc, o);
        if (lane >= o) sc += t;
    }
    if (lane == 31) wsum[wid] = sc;
    __syncthreads();
    if (wid == 0) {
        int s = wsum[lane];
        #pragma unroll
        for (int o = 1; o < 32; o <<= 1) {
            int t = __shfl_up_sync(0xffffffffu, s, o);
            if (lane >= o) s += t;
        }
        wsum[lane] = s;
    }
    __syncthreads();
    int warpoff = (wid > 0) ? wsum[wid - 1] : 0;
    if (i < n) g_off[i] = warpoff + sc - v;
    if (tid == 0) g_bsum[blockIdx.x] = wsum[31];
}

__global__ void k_scan2(int nb) {
    __shared__ int w0tot;
    int t = threadIdx.x, lane = t & 31, wid = t >> 5;
    int v = (t < nb) ? g_bsum[t] : 0;
    int sc = v;
    #pragma unroll
    for (int o = 1; o < 32; o <<= 1) {
        int x = __shfl_up_sync(0xffffffffu, sc, o);
        if (lane >= o) sc += x;
    }
    if (wid == 0 && lane == 31) w0tot = sc;
    __syncthreads();
    int excl = sc - v + (wid ? w0tot : 0);
    if (t < nb) g_bsum[t] = excl;
}

__global__ __launch_bounds__(1024) void k_scan3(int n) {
    int i = blockIdx.x * 1024 + threadIdx.x;
    if (i >= n) return;
    int o = g_off[i] + g_bsum[blockIdx.x];
    g_off[i] = o;
    g_cur[i] = o;
}

__global__ void k_fill(const int* __restrict__ src,
                       const int* __restrict__ dst, int E) {
    int i = blockIdx.x * blockDim.x + threadIdx.x;
    if (i >= E) return;
    int d = dst[i];
    int pos = atomicAdd(&g_cur[d], 1);
    g_csr[pos] = src[i];
}

// ---------------------------------------------------------------------------
// Split prep (fp16 hi/lo for x, single fp16 for W^T)
// ---------------------------------------------------------------------------
__global__ void k_split(const float* __restrict__ x, int M) {
    int i = blockIdx.x * blockDim.x + threadIdx.x;   // uint4 index (8 fp16)
    int total = MPAD * DIN / 8;
    if (i >= total) return;
    int row = i >> 5;
    float f[8];
    if (row < M) {
        const float4* p = (const float4*)(x + ((size_t)i << 3));
        float4 v0 = p[0], v1 = p[1];
        f[0] = v0.x; f[1] = v0.y; f[2] = v0.z; f[3] = v0.w;
        f[4] = v1.x; f[5] = v1.y; f[6] = v1.z; f[7] = v1.w;
    } else {
        #pragma unroll
        for (int j = 0; j < 8; j++) f[j] = 0.f;
    }
    uint32_t hi[4], lo[4];
    #pragma unroll
    for (int j = 0; j < 4; j++) {
        __half ha = __float2half_rn(f[j * 2]);
        __half hb = __float2half_rn(f[j * 2 + 1]);
        hi[j] = ((uint32_t)__half_as_ushort(hb) << 16) | __half_as_ushort(ha);
        __half la = __float2half_rn(f[j * 2] - __half2float(ha));
        __half lb = __float2half_rn(f[j * 2 + 1] - __half2float(hb));
        lo[j] = ((uint32_t)__half_as_ushort(lb) << 16) | __half_as_ushort(la);
    }
    ((uint4*)g_a_hi)[i] = make_uint4(hi[0], hi[1], hi[2], hi[3]);
    ((uint4*)g_a_lo)[i] = make_uint4(lo[0], lo[1], lo[2], lo[3]);
}

__global__ void k_wt(const float* __restrict__ W) {
    int i = blockIdx.x * blockDim.x + threadIdx.x;   // n*256 + k
    if (i >= DIN * DOUT) return;
    int n = i >> 8, k = i & 255;
    g_wt16[i] = __float2half_rn(W[k * DOUT + n]);
}

// ---------------------------------------------------------------------------
// WMMA GEMM half (fp16 2-pass): 128 output columns starting at nbase.
// Stage = {A_hi, A_lo, B} x 128 x LDS fp16; 2 stages double-buffered.
// ---------------------------------------------------------------------------
#define LDS 40
#define STAGE_ELEMS (128 * LDS)
#define STAGE_TOTAL (3 * STAGE_ELEMS)
#define SOUT_LD 132
#define SMEM_BYTES 69632   // max(2*STAGE_TOTAL*2 = 61440, epilogue 67584)

__global__ __launch_bounds__(256, 2) void k_gemm_wmma(int nbase) {
    extern __shared__ __align__(16) __half smd[];

    const int tid = threadIdx.x;
    const int w = tid >> 5;
    const int warp_m = w & 3;
    const int warp_n = w >> 2;
    const int Rbase = blockIdx.x * 128;
    const int Nbase = nbase;

    const int idx0 = tid * 2;
    const int r0 = idx0 >> 2, seg0 = idx0 & 3;
    const int r1 = (idx0 + 1) >> 2, seg1 = (idx0 + 1) & 3;

    auto prefetch = [&](int kc, int stage) {
        __half* base = smd + stage * STAGE_TOTAL;
        __half* dA_hi = base;
        __half* dA_lo = base + STAGE_ELEMS;
        __half* dB    = base + 2 * STAGE_ELEMS;
        __pipeline_memcpy_async(dA_hi + r0 * LDS + seg0 * 8,
            (const uint4*)g_a_hi + (size_t)(Rbase + r0) * 32 + kc * 4 + seg0, 16);
        __pipeline_memcpy_async(dA_hi + r1 * LDS + seg1 * 8,
            (const uint4*)g_a_hi + (size_t)(Rbase + r1) * 32 + kc * 4 + seg1, 16);
        __pipeline_memcpy_async(dA_lo + r0 * LDS + seg0 * 8,
            (const uint4*)g_a_lo + (size_t)(Rbase + r0) * 32 + kc * 4 + seg0, 16);
        __pipeline_memcpy_async(dA_lo + r1 * LDS + seg1 * 8,
            (const uint4*)g_a_lo + (size_t)(Rbase + r1) * 32 + kc * 4 + seg1, 16);
        __pipeline_memcpy_async(dB + r0 * LDS + seg0 * 8,
            (const uint4*)g_wt16 + (size_t)(Nbase + r0) * 32 + kc * 4 + seg0, 16);
        __pipeline_memcpy_async(dB + r1 * LDS + seg1 * 8,
            (const uint4*)g_wt16 + (size_t)(Nbase + r1) * 32 + kc * 4 + seg1, 16);
        __pipeline_commit();
    };

    wmma::fragment<wmma::accumulator, 16, 16, 16, float> acc[2][4];
    #pragma unroll
    for (int mi = 0; mi < 2; mi++)
        #pragma unroll
        for (int ni = 0; ni < 4; ni++)
            wmma::fill_fragment(acc[mi][ni], 0.0f);

    prefetch(0, 0);

    for (int kc = 0; kc < 8; kc++) {
        if (kc < 7) prefetch(kc + 1, (kc + 1) & 1);
        __pipeline_wait_prior(kc < 7 ? 1 : 0);
        __syncthreads();

        __half* base = smd + (kc & 1) * STAGE_TOTAL;
        __half* sA_hi = base;
        __half* sA_lo = base + STAGE_ELEMS;
        __half* sB    = base + 2 * STAGE_ELEMS;

        #pragma unroll
        for (int kk = 0; kk < 32; kk += 16) {
            wmma::fragment<wmma::matrix_a, 16, 16, 16, __half, wmma::row_major> ah[2], al[2];
            #pragma unroll
            for (int mi = 0; mi < 2; mi++) {
                wmma::load_matrix_sync(ah[mi], sA_hi + (warp_m * 32 + mi * 16) * LDS + kk, LDS);
                wmma::load_matrix_sync(al[mi], sA_lo + (warp_m * 32 + mi * 16) * LDS + kk, LDS);
            }
            wmma::fragment<wmma::matrix_b, 16, 16, 16, __half, wmma::col_major> bf[4];
            #pragma unroll
            for (int ni = 0; ni < 4; ni++)
                wmma::load_matrix_sync(bf[ni], sB + (warp_n * 64 + ni * 16) * LDS + kk, LDS);
            #pragma unroll
            for (int mi = 0; mi < 2; mi++)
                #pragma unroll
                for (int ni = 0; ni < 4; ni++) {
                    wmma::mma_sync(acc[mi][ni], ah[mi], bf[ni], acc[mi][ni]);
                    wmma::mma_sync(acc[mi][ni], al[mi], bf[ni], acc[mi][ni]);
                }
        }
        __syncthreads();
    }

    // ---- fp16 epilogue: frags -> padded smem tile -> coalesced writes ----
    float* sOut = (float*)smd;          // 128 x SOUT_LD floats = 67584 B
    #pragma unroll
    for (int mi = 0; mi < 2; mi++)
        #pragma unroll
        for (int ni = 0; ni < 4; ni++)
            wmma::store_matrix_sync(
                sOut + (warp_m * 32 + mi * 16) * SOUT_LD + warp_n * 64 + ni * 16,
                acc[mi][ni], SOUT_LD, wmma::mem_row_major);
    __syncthreads();

    #pragma unroll
    for (int j = 0; j < 8; j++) {
        int c = j * 256 + tid;
        int row = c >> 4;
        int u = c & 15;
        const float* src = sOut + row * SOUT_LD + u * 8;
        __half2 h[4];
        #pragma unroll
        for (int q = 0; q < 4; q++)
            h[q] = __floats2half2_rn(src[q * 2], src[q * 2 + 1]);
        *(uint4*)(g_h16 + (size_t)(Rbase + row) * DOUT + Nbase + u * 8) =
            *(const uint4*)h;
    }
}

// ---------------------------------------------------------------------------
// Node kernel half: one warp per node, 128 columns starting at col_base.
// ---------------------------------------------------------------------------
__device__ __forceinline__ void fma4h(uint2 v, float s, float* acc) {
    const __half2* h = (const __half2*)&v;
    float2 f0 = __half22float2(h[0]);
    float2 f1 = __half22float2(h[1]);
    acc[0] = fmaf(f0.x, s, acc[0]);
    acc[1] = fmaf(f0.y, s, acc[1]);
    acc[2] = fmaf(f1.x, s, acc[2]);
    acc[3] = fmaf(f1.y, s, acc[3]);
}

__global__ __launch_bounds__(256) void k_node(float* __restrict__ out,
                                              const float* __restrict__ b,
                                              const float* __restrict__ gamma,
                                              const float* __restrict__ beta,
                                              const float* __restrict__ mean,
                                              const float* __restrict__ var,
                                              int n, int col_base) {
    int warp = (blockIdx.x * blockDim.x + threadIdx.x) >> 5;
    int lane = threadIdx.x & 31;
    if (warp >= n) return;

    int node = warp;
    int start = g_off[node];
    int end   = start + g_degi[node];
    const size_t lane_off = col_base / 4 + lane;

    float acc[4] = {0.f, 0.f, 0.f, 0.f};

    int e = start;
    for (; e + 7 < end; e += 8) {
        int   s[8];
        float wgt[8];
        uint2 v[8];
        #pragma unroll
        for (int q = 0; q < 8; q++) s[q] = g_csr[e + q];
        #pragma unroll
        for (int q = 0; q < 8; q++) wgt[q] = g_dinv[s[q]];
        #pragma unroll
        for (int q = 0; q < 8; q++)
            v[q] = __ldg((const uint2*)(g_h16 + (size_t)s[q] * DOUT) + lane_off);
        #pragma unroll
        for (int q = 0; q < 8; q++) fma4h(v[q], wgt[q], acc);
    }
    for (; e < end; e++) {
        int s0 = g_csr[e];
        float w0 = g_dinv[s0];
        uint2 a = __ldg((const uint2*)(g_h16 + (size_t)s0 * DOUT) + lane_off);
        fma4h(a, w0, acc);
    }

    float di = g_dinv[node];
    {
        uint2 a = __ldg((const uint2*)(g_h16 + (size_t)node * DOUT) + lane_off);
        fma4h(a, di, acc);
    }
    #pragma unroll
    for (int k = 0; k < 4; k++) acc[k] *= di;

    int c4 = (col_base >> 2) + lane;
    float4 bv = ((const float4*)b)[c4];
    float4 gv = ((const float4*)gamma)[c4];
    float4 tv = ((const float4*)beta)[c4];
    float4 mv = ((const float4*)mean)[c4];
    float4 vv = ((const float4*)var)[c4];
    float4 r;
    float sx = gv.x * rsqrtf(vv.x + 1e-5f);
    float sy = gv.y * rsqrtf(vv.y + 1e-5f);
    float sz = gv.z * rsqrtf(vv.z + 1e-5f);
    float sw = gv.w * rsqrtf(vv.w + 1e-5f);
    r.x = fmaxf(fmaf(acc[0] + bv.x - mv.x, sx, tv.x), 0.f);
    r.y = fmaxf(fmaf(acc[1] + bv.y - mv.y, sy, tv.y), 0.f);
    r.z = fmaxf(fmaf(acc[2] + bv.z - mv.z, sz, tv.z), 0.f);
    r.w = fmaxf(fmaf(acc[3] + bv.w - mv.w, sw, tv.w), 0.f);
    ((float4*)(out + (size_t)node * DOUT))[c4] = r;
}

// ---------------------------------------------------------------------------
// Column-split pipeline (R13 layout):
//   main: wt -> split -> gemm0 -> gemm1 -> (csr) node1 -> (n0)
//   s2:   zero -> count -> scan1/2/3 -> fill  [ev_csr]
//   s3:   (ev_g0, ev_csr) node0  -- concurrent with gemm1
// ---------------------------------------------------------------------------
extern "C" void kernel_launch(void* const* d_in, const int* in_sizes, int n_in,
                              void* d_out, int out_size) {
    const float* x      = (const float*)d_in[0];
    const int*   ei     = (const int*)d_in[1];   // int32 (jax x64 disabled)
    const float* W      = (const float*)d_in[2];
    const float* b      = (const float*)d_in[3];
    const float* gamma  = (const float*)d_in[4];
    const float* beta   = (const float*)d_in[5];
    const float* rmean  = (const float*)d_in[6];
    const float* rvar   = (const float*)d_in[7];
    float* out = (float*)d_out;

    int N = in_sizes[0] / DIN;     // 50000
    int E = in_sizes[1] / 2;       // 800000
    const int* src = ei;
    const int* dst = ei + E;
    int nb = (N + 1023) / 1024;

    static cudaStream_t s2, s3;
    static cudaEvent_t ev_fork, ev_csr, ev_g0, ev_n0;
    static bool init_done = false;
    if (!init_done) {
        cudaFuncSetAttribute(k_gemm_wmma,
                             cudaFuncAttributeMaxDynamicSharedMemorySize,
                             SMEM_BYTES);
        cudaStreamCreateWithFlags(&s2, cudaStreamNonBlocking);
        cudaStreamCreateWithFlags(&s3, cudaStreamNonBlocking);
        cudaEventCreateWithFlags(&ev_fork, cudaEventDisableTiming);
        cudaEventCreateWithFlags(&ev_csr, cudaEventDisableTiming);
        cudaEventCreateWithFlags(&ev_g0, cudaEventDisableTiming);
        cudaEventCreateWithFlags(&ev_n0, cudaEventDisableTiming);
        init_done = true;
    }

    long long nthreads = (long long)N * 32;
    int node_blocks = (int)((nthreads + 255) / 256);
    dim3 ggrid(MPAD / 128, 1);

    // fork
    cudaEventRecord(ev_fork, 0);
    cudaStreamWaitEvent(s2, ev_fork, 0);
    cudaStreamWaitEvent(s3, ev_fork, 0);

    k_wt<<<(DIN * DOUT + 255) / 256, 256>>>(W);                    // launch 1
    int splitn = MPAD * DIN / 8;
    k_split<<<(splitn + 255) / 256, 256>>>(x, N);                  // launch 2
    k_zero<<<(N + 255) / 256, 256, 0, s2>>>(N);                    // launch 3

    k_gemm_wmma<<<ggrid, 256, SMEM_BYTES>>>(0);                    // launch 4 (profile)
    cudaEventRecord(ev_g0, 0);

    // CSR chain on s2
    k_count<<<(E + 255) / 256, 256, 0, s2>>>(dst, E);
    k_scan1<<<nb, 1024, 0, s2>>>(N);
    k_scan2<<<1, 64, 0, s2>>>(nb);
    k_scan3<<<nb, 1024, 0, s2>>>(N);
    k_fill<<<(E + 255) / 256, 256, 0, s2>>>(src, dst, E);
    cudaEventRecord(ev_csr, s2);

    // gemm1 on main, node0 on s3 (concurrent)
    k_gemm_wmma<<<ggrid, 256, SMEM_BYTES>>>(128);
    cudaStreamWaitEvent(s3, ev_g0, 0);
    cudaStreamWaitEvent(s3, ev_csr, 0);
    k_node<<<node_blocks, 256, 0, s3>>>(out, b, gamma, beta, rmean, rvar, N, 0);
    cudaEventRecord(ev_n0, s3);

    // node1 on main after gemm1 + csr
    cudaStreamWaitEvent(0, ev_csr, 0);
    k_node<<<node_blocks, 256, 0, 0>>>(out, b, gamma, beta, rmean, rvar, N, 128);

    // join node0 back into origin stream
    cudaStreamWaitEvent(0, ev_n0, 0);
}

// round 15
// speedup vs baseline: 1.5711x; 1.1779x over previous
#include <cuda_runtime.h>
#include <cuda_fp16.h>
#include <cuda_pipeline.h>
#include <mma.h>
#include <cstdint>

using namespace nvcuda;

#define NNODES 50000
#define MPAD   50048          // 391 * 128
#define EMAX   800000
#define DOUT   256
#define DIN    256

// ---------------------------------------------------------------------------
// Scratch (device globals)
// ---------------------------------------------------------------------------
__device__ __half g_h16[(size_t)MPAD * DOUT];    // x @ W in fp16 (gather source)
__device__ int   g_degi[NNODES];
__device__ int   g_off[NNODES];
__device__ int   g_cur[NNODES];
__device__ float g_dinv[NNODES];
__device__ int   g_csr[EMAX];
__device__ int   g_bsum[64];
__device__ __half g_a16[(size_t)MPAD * DIN];     // x in fp16
__device__ __half g_wt16[DOUT * DIN];            // W^T fp16 [n][k]

// ---------------------------------------------------------------------------
// Degree / CSR build
// ---------------------------------------------------------------------------
__global__ void k_zero(int n) {
    int i = blockIdx.x * blockDim.x + threadIdx.x;
    if (i < n) g_degi[i] = 0;
}
__global__ void k_count(const int* __restrict__ dst, int E) {
    int i = blockIdx.x * blockDim.x + threadIdx.x;
    if (i < E) atomicAdd(&g_degi[dst[i]], 1);
}

__global__ __launch_bounds__(1024) void k_scan1(int n) {
    __shared__ int wsum[32];
    int tid = threadIdx.x, lane = tid & 31, wid = tid >> 5;
    int i = blockIdx.x * 1024 + tid;
    int v = (i < n) ? g_degi[i] : 0;
    if (i < n) g_dinv[i] = rsqrtf((float)(v + 1));
    int sc = v;
    #pragma unroll
    for (int o = 1; o < 32; o <<= 1) {
        int t = __shfl_up_sync(0xffffffffu, sc, o);
        if (lane >= o) sc += t;
    }
    if (lane == 31) wsum[wid] = sc;
    __syncthreads();
    if (wid == 0) {
        int s = wsum[lane];
        #pragma unroll
        for (int o = 1; o < 32; o <<= 1) {
            int t = __shfl_up_sync(0xffffffffu, s, o);
            if (lane >= o) s += t;
        }
        wsum[lane] = s;
    }
    __syncthreads();
    int warpoff = (wid > 0) ? wsum[wid - 1] : 0;
    if (i < n) g_off[i] = warpoff + sc - v;
    if (tid == 0) g_bsum[blockIdx.x] = wsum[31];
}

__global__ void k_scan2(int nb) {
    __shared__ int w0tot;
    int t = threadIdx.x, lane = t & 31, wid = t >> 5;
    int v = (t < nb) ? g_bsum[t] : 0;
    int sc = v;
    #pragma unroll
    for (int o = 1; o < 32; o <<= 1) {
        int x = __shfl_up_sync(0xffffffffu, sc, o);
        if (lane >= o) sc += x;
    }
    if (wid == 0 && lane == 31) w0tot = sc;
    __syncthreads();
    int excl = sc - v + (wid ? w0tot : 0);
    if (t < nb) g_bsum[t] = excl;
}

__global__ __launch_bounds__(1024) void k_scan3(int n) {
    int i = blockIdx.x * 1024 + threadIdx.x;
    if (i >= n) return;
    int o = g_off[i] + g_bsum[blockIdx.x];
    g_off[i] = o;
    g_cur[i] = o;
}

__global__ void k_fill(const int* __restrict__ src,
                       const int* __restrict__ dst, int E) {
    int i = blockIdx.x * blockDim.x + threadIdx.x;
    if (i >= E) return;
    int d = dst[i];
    int pos = atomicAdd(&g_cur[d], 1);
    g_csr[pos] = src[i];
}

// ---------------------------------------------------------------------------
// Prep: x -> fp16, W -> fp16 W^T
// ---------------------------------------------------------------------------
__global__ void k_split(const float* __restrict__ x, int M) {
    int i = blockIdx.x * blockDim.x + threadIdx.x;   // uint4 index (8 fp16)
    int total = MPAD * DIN / 8;
    if (i >= total) return;
    int row = i >> 5;
    uint32_t h[4];
    if (row < M) {
        const float4* p = (const float4*)(x + ((size_t)i << 3));
        float4 v0 = p[0], v1 = p[1];
        __half2 h0 = __floats2half2_rn(v0.x, v0.y);
        __half2 h1 = __floats2half2_rn(v0.z, v0.w);
        __half2 h2 = __floats2half2_rn(v1.x, v1.y);
        __half2 h3 = __floats2half2_rn(v1.z, v1.w);
        h[0] = *(uint32_t*)&h0; h[1] = *(uint32_t*)&h1;
        h[2] = *(uint32_t*)&h2; h[3] = *(uint32_t*)&h3;
    } else {
        h[0] = h[1] = h[2] = h[3] = 0;
    }
    ((uint4*)g_a16)[i] = make_uint4(h[0], h[1], h[2], h[3]);
}

__global__ void k_wt(const float* __restrict__ W) {
    int i = blockIdx.x * blockDim.x + threadIdx.x;   // n*256 + k
    if (i >= DIN * DOUT) return;
    int n = i >> 8, k = i & 255;
    g_wt16[i] = __float2half_rn(W[k * DOUT + n]);
}

// ---------------------------------------------------------------------------
// WMMA GEMM half (fp16 1-pass): 128 output columns starting at nbase.
// Stage = {A, B} x 128 x LDS fp16; 2 stages double-buffered (40 KB).
// ---------------------------------------------------------------------------
#define LDS 40
#define STAGE_ELEMS (128 * LDS)
#define STAGE_TOTAL (2 * STAGE_ELEMS)
#define SOUT_LD 132
#define SMEM_BYTES 69632   // epilogue tile 128*132*4 = 67584 dominates

__global__ __launch_bounds__(256, 2) void k_gemm_wmma(int nbase) {
    extern __shared__ __align__(16) __half smd[];

    const int tid = threadIdx.x;
    const int w = tid >> 5;
    const int warp_m = w & 3;
    const int warp_n = w >> 2;
    const int Rbase = blockIdx.x * 128;
    const int Nbase = nbase;

    const int idx0 = tid * 2;
    const int r0 = idx0 >> 2, seg0 = idx0 & 3;
    const int r1 = (idx0 + 1) >> 2, seg1 = (idx0 + 1) & 3;

    auto prefetch = [&](int kc, int stage) {
        __half* dA = smd + stage * STAGE_TOTAL;
        __half* dB = dA + STAGE_ELEMS;
        __pipeline_memcpy_async(dA + r0 * LDS + seg0 * 8,
            (const uint4*)g_a16 + (size_t)(Rbase + r0) * 32 + kc * 4 + seg0, 16);
        __pipeline_memcpy_async(dA + r1 * LDS + seg1 * 8,
            (const uint4*)g_a16 + (size_t)(Rbase + r1) * 32 + kc * 4 + seg1, 16);
        __pipeline_memcpy_async(dB + r0 * LDS + seg0 * 8,
            (const uint4*)g_wt16 + (size_t)(Nbase + r0) * 32 + kc * 4 + seg0, 16);
        __pipeline_memcpy_async(dB + r1 * LDS + seg1 * 8,
            (const uint4*)g_wt16 + (size_t)(Nbase + r1) * 32 + kc * 4 + seg1, 16);
        __pipeline_commit();
    };

    wmma::fragment<wmma::accumulator, 16, 16, 16, float> acc[2][4];
    #pragma unroll
    for (int mi = 0; mi < 2; mi++)
        #pragma unroll
        for (int ni = 0; ni < 4; ni++)
            wmma::fill_fragment(acc[mi][ni], 0.0f);

    prefetch(0, 0);

    for (int kc = 0; kc < 8; kc++) {
        if (kc < 7) prefetch(kc + 1, (kc + 1) & 1);
        __pipeline_wait_prior(kc < 7 ? 1 : 0);
        __syncthreads();

        __half* sA = smd + (kc & 1) * STAGE_TOTAL;
        __half* sB = sA + STAGE_ELEMS;

        #pragma unroll
        for (int kk = 0; kk < 32; kk += 16) {
            wmma::fragment<wmma::matrix_a, 16, 16, 16, __half, wmma::row_major> af[2];
            #pragma unroll
            for (int mi = 0; mi < 2; mi++)
                wmma::load_matrix_sync(af[mi], sA + (warp_m * 32 + mi * 16) * LDS + kk, LDS);
            wmma::fragment<wmma::matrix_b, 16, 16, 16, __half, wmma::col_major> bf[4];
            #pragma unroll
            for (int ni = 0; ni < 4; ni++)
                wmma::load_matrix_sync(bf[ni], sB + (warp_n * 64 + ni * 16) * LDS + kk, LDS);
            #pragma unroll
            for (int mi = 0; mi < 2; mi++)
                #pragma unroll
                for (int ni = 0; ni < 4; ni++)
                    wmma::mma_sync(acc[mi][ni], af[mi], bf[ni], acc[mi][ni]);
        }
        __syncthreads();
    }

    // ---- fp16 epilogue: frags -> padded smem tile -> coalesced writes ----
    float* sOut = (float*)smd;          // 128 x SOUT_LD floats = 67584 B
    #pragma unroll
    for (int mi = 0; mi < 2; mi++)
        #pragma unroll
        for (int ni = 0; ni < 4; ni++)
            wmma::store_matrix_sync(
                sOut + (warp_m * 32 + mi * 16) * SOUT_LD + warp_n * 64 + ni * 16,
                acc[mi][ni], SOUT_LD, wmma::mem_row_major);
    __syncthreads();

    #pragma unroll
    for (int j = 0; j < 8; j++) {
        int c = j * 256 + tid;
        int row = c >> 4;
        int u = c & 15;
        const float* src = sOut + row * SOUT_LD + u * 8;
        __half2 h[4];
        #pragma unroll
        for (int q = 0; q < 4; q++)
            h[q] = __floats2half2_rn(src[q * 2], src[q * 2 + 1]);
        *(uint4*)(g_h16 + (size_t)(Rbase + row) * DOUT + Nbase + u * 8) =
            *(const uint4*)h;
    }
}

// ---------------------------------------------------------------------------
// Node kernel half: one warp per node, 128 columns starting at col_base.
// ---------------------------------------------------------------------------
__device__ __forceinline__ void fma4h(uint2 v, float s, float* acc) {
    const __half2* h = (const __half2*)&v;
    float2 f0 = __half22float2(h[0]);
    float2 f1 = __half22float2(h[1]);
    acc[0] = fmaf(f0.x, s, acc[0]);
    acc[1] = fmaf(f0.y, s, acc[1]);
    acc[2] = fmaf(f1.x, s, acc[2]);
    acc[3] = fmaf(f1.y, s, acc[3]);
}

__global__ __launch_bounds__(256) void k_node(float* __restrict__ out,
                                              const float* __restrict__ b,
                                              const float* __restrict__ gamma,
                                              const float* __restrict__ beta,
                                              const float* __restrict__ mean,
                                              const float* __restrict__ var,
                                              int n, int col_base) {
    int warp = (blockIdx.x * blockDim.x + threadIdx.x) >> 5;
    int lane = threadIdx.x & 31;
    if (warp >= n) return;

    int node = warp;
    int start = g_off[node];
    int end   = start + g_degi[node];
    const size_t lane_off = col_base / 4 + lane;

    float acc[4] = {0.f, 0.f, 0.f, 0.f};

    int e = start;
    for (; e + 7 < end; e += 8) {
        int   s[8];
        float wgt[8];
        uint2 v[8];
        #pragma unroll
        for (int q = 0; q < 8; q++) s[q] = g_csr[e + q];
        #pragma unroll
        for (int q = 0; q < 8; q++) wgt[q] = g_dinv[s[q]];
        #pragma unroll
        for (int q = 0; q < 8; q++)
            v[q] = __ldg((const uint2*)(g_h16 + (size_t)s[q] * DOUT) + lane_off);
        #pragma unroll
        for (int q = 0; q < 8; q++) fma4h(v[q], wgt[q], acc);
    }
    for (; e < end; e++) {
        int s0 = g_csr[e];
        float w0 = g_dinv[s0];
        uint2 a = __ldg((const uint2*)(g_h16 + (size_t)s0 * DOUT) + lane_off);
        fma4h(a, w0, acc);
    }

    float di = g_dinv[node];
    {
        uint2 a = __ldg((const uint2*)(g_h16 + (size_t)node * DOUT) + lane_off);
        fma4h(a, di, acc);
    }
    #pragma unroll
    for (int k = 0; k < 4; k++) acc[k] *= di;

    int c4 = (col_base >> 2) + lane;
    float4 bv = ((const float4*)b)[c4];
    float4 gv = ((const float4*)gamma)[c4];
    float4 tv = ((const float4*)beta)[c4];
    float4 mv = ((const float4*)mean)[c4];
    float4 vv = ((const float4*)var)[c4];
    float4 r;
    float sx = gv.x * rsqrtf(vv.x + 1e-5f);
    float sy = gv.y * rsqrtf(vv.y + 1e-5f);
    float sz = gv.z * rsqrtf(vv.z + 1e-5f);
    float sw = gv.w * rsqrtf(vv.w + 1e-5f);
    r.x = fmaxf(fmaf(acc[0] + bv.x - mv.x, sx, tv.x), 0.f);
    r.y = fmaxf(fmaf(acc[1] + bv.y - mv.y, sy, tv.y), 0.f);
    r.z = fmaxf(fmaf(acc[2] + bv.z - mv.z, sz, tv.z), 0.f);
    r.w = fmaxf(fmaf(acc[3] + bv.w - mv.w, sw, tv.w), 0.f);
    ((float4*)(out + (size_t)node * DOUT))[c4] = r;
}

// ---------------------------------------------------------------------------
// Column-split pipeline:
//   main: wt -> split -> gemm0 -> gemm1 -> (csr) node1 -> (n0)
//   s2:   zero -> count -> scan1/2/3 -> fill  [ev_csr]
//   s3:   (ev_g0, ev_csr) node0  -- concurrent with gemm1
// ---------------------------------------------------------------------------
extern "C" void kernel_launch(void* const* d_in, const int* in_sizes, int n_in,
                              void* d_out, int out_size) {
    const float* x      = (const float*)d_in[0];
    const int*   ei     = (const int*)d_in[1];   // int32 (jax x64 disabled)
    const float* W      = (const float*)d_in[2];
    const float* b      = (const float*)d_in[3];
    const float* gamma  = (const float*)d_in[4];
    const float* beta   = (const float*)d_in[5];
    const float* rmean  = (const float*)d_in[6];
    const float* rvar   = (const float*)d_in[7];
    float* out = (float*)d_out;

    int N = in_sizes[0] / DIN;     // 50000
    int E = in_sizes[1] / 2;       // 800000
    const int* src = ei;
    const int* dst = ei + E;
    int nb = (N + 1023) / 1024;

    static cudaStream_t s2, s3;
    static cudaEvent_t ev_fork, ev_csr, ev_g0, ev_n0;
    static bool init_done = false;
    if (!init_done) {
        cudaFuncSetAttribute(k_gemm_wmma,
                             cudaFuncAttributeMaxDynamicSharedMemorySize,
                             SMEM_BYTES);
        cudaStreamCreateWithFlags(&s2, cudaStreamNonBlocking);
        cudaStreamCreateWithFlags(&s3, cudaStreamNonBlocking);
        cudaEventCreateWithFlags(&ev_fork, cudaEventDisableTiming);
        cudaEventCreateWithFlags(&ev_csr, cudaEventDisableTiming);
        cudaEventCreateWithFlags(&ev_g0, cudaEventDisableTiming);
        cudaEventCreateWithFlags(&ev_n0, cudaEventDisableTiming);
        init_done = true;
    }

    long long nthreads = (long long)N * 32;
    int node_blocks = (int)((nthreads + 255) / 256);
    dim3 ggrid(MPAD / 128, 1);

    // fork
    cudaEventRecord(ev_fork, 0);
    cudaStreamWaitEvent(s2, ev_fork, 0);
    cudaStreamWaitEvent(s3, ev_fork, 0);

    k_wt<<<(DIN * DOUT + 255) / 256, 256>>>(W);                    // launch 1
    int splitn = MPAD * DIN / 8;
    k_split<<<(splitn + 255) / 256, 256>>>(x, N);                  // launch 2
    k_zero<<<(N + 255) / 256, 256, 0, s2>>>(N);                    // launch 3

    k_gemm_wmma<<<ggrid, 256, SMEM_BYTES>>>(0);                    // launch 4 (profile)
    cudaEventRecord(ev_g0, 0);

    // CSR chain on s2
    k_count<<<(E + 255) / 256, 256, 0, s2>>>(dst, E);
    k_scan1<<<nb, 1024, 0, s2>>>(N);
    k_scan2<<<1, 64, 0, s2>>>(nb);
    k_scan3<<<nb, 1024, 0, s2>>>(N);
    k_fill<<<(E + 255) / 256, 256, 0, s2>>>(src, dst, E);
    cudaEventRecord(ev_csr, s2);

    // gemm1 on main, node0 on s3 (concurrent)
    k_gemm_wmma<<<ggrid, 256, SMEM_BYTES>>>(128);
    cudaStreamWaitEvent(s3, ev_g0, 0);
    cudaStreamWaitEvent(s3, ev_csr, 0);
    k_node<<<node_blocks, 256, 0, s3>>>(out, b, gamma, beta, rmean, rvar, N, 0);
    cudaEventRecord(ev_n0, s3);

    // node1 on main after gemm1 + csr
    cudaStreamWaitEvent(0, ev_csr, 0);
    k_node<<<node_blocks, 256, 0, 0>>>(out, b, gamma, beta, rmean, rvar, N, 128);

    // join node0 back into origin stream
    cudaStreamWaitEvent(0, ev_n0, 0);
}